// round 10
// baseline (speedup 1.0000x reference)
#include <cuda_runtime.h>
#include <cstdint>

// Problem constants (fixed by the reference).
#define N_KEYS   65536
#define EMB      1024
#define KSEL     512
#define BATCH    128
#define NBINS    65536   // top 16 bits of ordered float. R9: 4096 bins caused
                         // L2 same-address atomic serialization (~12us); 65536
                         // bins measured 43.6us sim in R3.
#define CAND_CAP 2048    // candidate capacity (expected ~540 used)

// -------- scratch (no allocations allowed: __device__ globals) --------
// Zero-initialized at module load; each kernel re-arms its own counters
// before exiting, so the invariant holds for the correctness run and for
// every CUDA-graph replay.
__device__ float              g_sims[N_KEYS];
__device__ unsigned int       g_hist[NBINS];
__device__ unsigned int       g_T;                 // rank-512 bin threshold
__device__ unsigned long long g_cand[CAND_CAP];
__device__ unsigned int       g_ccnt;
__device__ int                g_topk[KSEL];
__device__ unsigned int       g_done1, g_done2;

// Monotone float -> uint transform: a > b  <=>  ford(a) > ford(b)
__device__ __forceinline__ unsigned int ford(float f) {
    unsigned int u = __float_as_uint(f);
    return (u & 0x80000000u) ? ~u : (u | 0x80000000u);
}

// ---------------------------------------------------------------------
// K1: sims + histogram (DRAM-bound). Last block's tail scans the 256 KB
// histogram with a two-level parallel suffix scan (no serial L2 loops).
// One warp per key row, 8 warps/block, grid = 8192.
// ---------------------------------------------------------------------
__global__ void __launch_bounds__(256)
sim_kernel(const float* __restrict__ keys,
           const float* __restrict__ query) {
    const int warp = threadIdx.x >> 5;
    const int lane = threadIdx.x & 31;
    const int n    = blockIdx.x * 8 + warp;
    const int t    = threadIdx.x;

    {
        const float4* k4 = reinterpret_cast<const float4*>(keys) + (size_t)n * (EMB / 4);
        const float4* q4 = reinterpret_cast<const float4*>(query);

        float dot = 0.f, sq = 0.f;
#pragma unroll
        for (int l = 0; l < 8; ++l) {
            float4 kv = k4[lane + 32 * l];               // plain cached load (R3 path)
            float4 qv = __ldg(&q4[lane + 32 * l]);
            dot = fmaf(kv.x, qv.x, dot);
            dot = fmaf(kv.y, qv.y, dot);
            dot = fmaf(kv.z, qv.z, dot);
            dot = fmaf(kv.w, qv.w, dot);
            sq  = fmaf(kv.x, kv.x, sq);
            sq  = fmaf(kv.y, kv.y, sq);
            sq  = fmaf(kv.z, kv.z, sq);
            sq  = fmaf(kv.w, kv.w, sq);
        }
#pragma unroll
        for (int o = 16; o > 0; o >>= 1) {
            dot += __shfl_xor_sync(0xFFFFFFFFu, dot, o);
            sq  += __shfl_xor_sync(0xFFFFFFFFu, sq,  o);
        }
        if (lane == 0) {
            float nrm = __fsqrt_rn(fmaxf(sq, 1e-16f));   // max(norm, 1e-8)
            float sim = __fdiv_rn(dot, nrm);             // q-norm scale omitted (order-invariant)
            g_sims[n] = sim;
            atomicAdd(&g_hist[ford(sim) >> 16], 1u);     // 16-bit bins: low contention
        }
    }

    // last-block election
    __shared__ unsigned int s_is_last;
    __syncthreads();
    if (t == 0) {
        __threadfence();
        s_is_last = (atomicAdd(&g_done1, 1u) == gridDim.x - 1) ? 1u : 0u;
    }
    __syncthreads();
    if (!s_is_last) return;
    __threadfence();

    // ---- threshold: two-level suffix scan over 65536 bins ----
    __shared__ int s_sum[256];      // level 1: 256 chunks of 256 bins
    __shared__ int s_bins[256];     // level 2: bins of the winning chunk
    __shared__ int s_tstar, s_bstar;

    {   // per-thread sum over 256 consecutive bins (64x uint4)
        const uint4* h4 = reinterpret_cast<const uint4*>(g_hist) + t * 64;
        unsigned int s = 0;
#pragma unroll 8
        for (int i = 0; i < 64; ++i) { uint4 v = h4[i]; s += v.x + v.y + v.z + v.w; }
        s_sum[t] = (int)s;
    }
    __syncthreads();

    // Hillis-Steele suffix scan over 256 chunks
    for (int d = 1; d < 256; d <<= 1) {
        int v = s_sum[t] + ((t + d < 256) ? s_sum[t + d] : 0);
        __syncthreads();
        s_sum[t] = v;
        __syncthreads();
    }

    if (s_sum[t] >= KSEL && (t == 255 || s_sum[t + 1] < KSEL)) s_tstar = t;
    __syncthreads();
    const int tstar = s_tstar;
    const int base  = (tstar < 255) ? s_sum[tstar + 1] : 0;  // count above chunk

    // level 2: suffix scan the 256 bins of the winning chunk
    s_bins[t] = (int)g_hist[tstar * 256 + t];
    __syncthreads();
    for (int d = 1; d < 256; d <<= 1) {
        int v = s_bins[t] + ((t + d < 256) ? s_bins[t + d] : 0);
        __syncthreads();
        s_bins[t] = v;
        __syncthreads();
    }
    // largest bin b with base + suffix(b) >= KSEL
    if (base + s_bins[t] >= KSEL && (t == 255 || base + s_bins[t + 1] < KSEL)) s_bstar = t;
    __syncthreads();
    if (t == 0) g_T = ((unsigned int)(tstar * 256 + s_bstar)) << 16;
    __syncthreads();   // all reads of g_hist done before re-zeroing below

    // re-arm for next invocation (each thread zeroes its own 256 bins)
    {
        uint4 z = make_uint4(0u, 0u, 0u, 0u);
        uint4* h4 = reinterpret_cast<uint4*>(g_hist) + t * 64;
#pragma unroll 8
        for (int i = 0; i < 64; ++i) h4[i] = z;
        if (t == 0) g_done1 = 0u;
    }
}

// ---------------------------------------------------------------------
// K2: GRID-PARALLEL candidate compaction (16 blocks x 1024 threads read
// g_sims once against g_T; ~540 global atomics total), then the last
// block does the exact O(n^2) rank placement in smem.
// key = (ord<<32)|~idx  =>  rank order == jax top_k (desc value, asc index)
// ---------------------------------------------------------------------
__global__ void __launch_bounds__(1024)
compact_rank_kernel() {
    const int t  = threadIdx.x;
    const unsigned int T = g_T;                          // written by K1 (stream-ordered)

    {   // one float4 of g_sims per thread
        const int i4 = blockIdx.x * 1024 + t;            // 0..16383
        float4 v = reinterpret_cast<const float4*>(g_sims)[i4];
        unsigned int u0 = ford(v.x), u1 = ford(v.y), u2 = ford(v.z), u3 = ford(v.w);
        int base = i4 * 4;
        if (u0 >= T) { unsigned int p = atomicAdd(&g_ccnt, 1u); if (p < CAND_CAP)
            g_cand[p] = ((unsigned long long)u0 << 32) | (unsigned int)~(unsigned int)(base + 0); }
        if (u1 >= T) { unsigned int p = atomicAdd(&g_ccnt, 1u); if (p < CAND_CAP)
            g_cand[p] = ((unsigned long long)u1 << 32) | (unsigned int)~(unsigned int)(base + 1); }
        if (u2 >= T) { unsigned int p = atomicAdd(&g_ccnt, 1u); if (p < CAND_CAP)
            g_cand[p] = ((unsigned long long)u2 << 32) | (unsigned int)~(unsigned int)(base + 2); }
        if (u3 >= T) { unsigned int p = atomicAdd(&g_ccnt, 1u); if (p < CAND_CAP)
            g_cand[p] = ((unsigned long long)u3 << 32) | (unsigned int)~(unsigned int)(base + 3); }
    }

    // last-block election
    __shared__ unsigned int s_is_last;
    __syncthreads();
    if (t == 0) {
        __threadfence();
        s_is_last = (atomicAdd(&g_done2, 1u) == gridDim.x - 1) ? 1u : 0u;
    }
    __syncthreads();
    if (!s_is_last) return;
    __threadfence();

    // ---- exact ranking of ~540 candidates on 1024 threads ----
    __shared__ unsigned long long s_key[CAND_CAP];
    const unsigned int ccnt = g_ccnt;
    const int cnt = (ccnt < CAND_CAP) ? (int)ccnt : CAND_CAP;

    for (int i = t; i < cnt; i += 1024) s_key[i] = g_cand[i];
    __syncthreads();

    for (int i = t; i < cnt; i += 1024) {
        const unsigned long long ki = s_key[i];
        int rank = 0;
        for (int j = 0; j < cnt; ++j)                    // broadcast smem reads
            rank += (s_key[j] > ki);
        if (rank < KSEL)
            g_topk[rank] = (int)(~(unsigned int)(ki & 0xFFFFFFFFull));
    }

    // re-arm for next invocation (after all reads of g_ccnt above)
    __syncthreads();
    if (t == 0) { g_ccnt = 0u; g_done2 = 0u; }
}

// ---------------------------------------------------------------------
// K3: out[b,k,:] = x[b,k,:] + prompts[topk[k], :]
// One block per (b,k) row; thread t handles float4 t of the row.
// x/out streamed (cs hints measured faster HERE: 83.3 -> 80.4us) so the
// 512 selected prompt rows (2 MB) stay L2-resident across all batches.
// ---------------------------------------------------------------------
__global__ void __launch_bounds__(256)
add_kernel(const float4* __restrict__ x,
           const float4* __restrict__ prompts,
           float4* __restrict__ out) {
    const int bid = blockIdx.x;            // b*512 + k
    const int k   = bid & (KSEL - 1);
    const int t   = threadIdx.x;           // 0..255
    const int row = g_topk[k];

    const size_t xo = (size_t)bid * (EMB / 4) + t;
    float4 xv = __ldcs(&x[xo]);                          // streaming read-once
    float4 pv = __ldg(&prompts[(size_t)row * (EMB / 4) + t]);
    xv.x += pv.x; xv.y += pv.y; xv.z += pv.z; xv.w += pv.w;
    __stcs(&out[xo], xv);                                // streaming write-once
}

// ---------------------------------------------------------------------
extern "C" void kernel_launch(void* const* d_in, const int* in_sizes, int n_in,
                              void* d_out, int out_size) {
    const float* x       = (const float*)d_in[0];   // [128, 512, 1024]
    const float* query   = (const float*)d_in[1];   // [1024]
    const float* keys    = (const float*)d_in[2];   // [65536, 1024]
    const float* prompts = (const float*)d_in[3];   // [65536, 1024]
    float* out           = (float*)d_out;           // [128, 512, 1024]

    sim_kernel<<<N_KEYS / 8, 256>>>(keys, query);
    compact_rank_kernel<<<16, 1024>>>();
    add_kernel<<<BATCH * KSEL, 256>>>(reinterpret_cast<const float4*>(x),
                                      reinterpret_cast<const float4*>(prompts),
                                      reinterpret_cast<float4*>(out));
}

// round 11
// speedup vs baseline: 1.1656x; 1.1656x over previous
#include <cuda_runtime.h>
#include <cstdint>

// Problem constants (fixed by the reference).
#define N_KEYS   65536
#define EMB      1024
#define KSEL     512
#define BATCH    128
#define NBINS    4096    // top 12 bits of ordered float (16 KB hist).
                         // R10 finding: bin count was never the sim cost —
                         // the in-K1 single-block tail was (13-27us). K1 now
                         // has NO tail; threshold moved to K2 (parallel).
#define CAND_CAP 2048    // candidate capacity (expected ~540 used)

// -------- scratch (no allocations allowed: __device__ globals) --------
// Zero-initialized at module load; K2's last block re-arms g_hist/g_ccnt/
// g_done2 before exiting, so the invariant holds for the correctness run
// and for every CUDA-graph replay.
__device__ float              g_sims[N_KEYS];
__device__ unsigned int       g_hist[NBINS];
__device__ unsigned long long g_cand[CAND_CAP];
__device__ unsigned int       g_ccnt;
__device__ int                g_topk[KSEL];
__device__ unsigned int       g_done2;

// Monotone float -> uint transform: a > b  <=>  ford(a) > ford(b)
__device__ __forceinline__ unsigned int ford(float f) {
    unsigned int u = __float_as_uint(f);
    return (u & 0x80000000u) ? ~u : (u | 0x80000000u);
}

// ---------------------------------------------------------------------
// K1: PURE sims + histogram (DRAM-bound). No tail, no election, no fence
// — exactly the R3 structure that measured 43.6us @ 78.9% DRAM.
// One warp per key row, 8 warps/block, grid = 8192.
// ---------------------------------------------------------------------
__global__ void __launch_bounds__(256)
sim_kernel(const float* __restrict__ keys,
           const float* __restrict__ query) {
    const int warp = threadIdx.x >> 5;
    const int lane = threadIdx.x & 31;
    const int n    = blockIdx.x * 8 + warp;

    const float4* k4 = reinterpret_cast<const float4*>(keys) + (size_t)n * (EMB / 4);
    const float4* q4 = reinterpret_cast<const float4*>(query);

    float dot = 0.f, sq = 0.f;
#pragma unroll
    for (int l = 0; l < 8; ++l) {
        float4 kv = k4[lane + 32 * l];
        float4 qv = __ldg(&q4[lane + 32 * l]);
        dot = fmaf(kv.x, qv.x, dot);
        dot = fmaf(kv.y, qv.y, dot);
        dot = fmaf(kv.z, qv.z, dot);
        dot = fmaf(kv.w, qv.w, dot);
        sq  = fmaf(kv.x, kv.x, sq);
        sq  = fmaf(kv.y, kv.y, sq);
        sq  = fmaf(kv.z, kv.z, sq);
        sq  = fmaf(kv.w, kv.w, sq);
    }
#pragma unroll
    for (int o = 16; o > 0; o >>= 1) {
        dot += __shfl_xor_sync(0xFFFFFFFFu, dot, o);
        sq  += __shfl_xor_sync(0xFFFFFFFFu, sq,  o);
    }
    if (lane == 0) {
        float nrm = __fsqrt_rn(fmaxf(sq, 1e-16f));   // max(norm, 1e-8)
        float sim = __fdiv_rn(dot, nrm);             // q-norm scale omitted (order-invariant)
        g_sims[n] = sim;
        atomicAdd(&g_hist[ford(sim) >> 20], 1u);     // result unused -> RED.ADD
    }
}

// ---------------------------------------------------------------------
// K2: 16 blocks x 1024 threads.
//  Phase A (every block, redundantly, in parallel): threshold from the
//    16 KB histogram — one uint4 of bins per thread, block-wide suffix
//    scan. No inter-block dependency, ~2us.
//  Phase B: each block compacts its 1/16 slice of g_sims vs T
//    (~540 global atomics total).
//  Phase C (last block): exact O(n^2) rank placement of candidates.
//    key = (ord<<32)|~idx => rank order == jax top_k (desc val, asc idx).
//    Then re-arm g_hist/g_ccnt/g_done2 (all hist readers have finished:
//    their reads precede their election arrivals).
// ---------------------------------------------------------------------
__global__ void __launch_bounds__(1024)
compact_rank_kernel() {
    const int t = threadIdx.x;

    // ---- Phase A: threshold (redundant per block) ----
    __shared__ int          s_sum[1024];
    __shared__ int          s_tstar;
    __shared__ unsigned int s_T;

    const uint4 h = reinterpret_cast<const uint4*>(g_hist)[t];   // bins 4t..4t+3
    s_sum[t] = (int)(h.x + h.y + h.z + h.w);
    __syncthreads();

    // Hillis-Steele suffix scan: s_sum[t] = count of sims in bins >= 4t
    for (int d = 1; d < 1024; d <<= 1) {
        int v = s_sum[t] + ((t + d < 1024) ? s_sum[t + d] : 0);
        __syncthreads();
        s_sum[t] = v;
        __syncthreads();
    }

    if (s_sum[t] >= KSEL && (t == 1023 || s_sum[t + 1] < KSEL)) s_tstar = t;
    __syncthreads();

    if (t == s_tstar) {                          // exactly one thread; owns h
        int cum = (t < 1023) ? s_sum[t + 1] : 0;
        int bb;
        cum += (int)h.w; if (cum >= KSEL) bb = 3;
        else { cum += (int)h.z; if (cum >= KSEL) bb = 2;
        else { cum += (int)h.y; if (cum >= KSEL) bb = 1; else bb = 0; } }
        s_T = ((unsigned int)(t * 4 + bb)) << 20;
    }
    __syncthreads();
    const unsigned int T = s_T;

    // ---- Phase B: compact this block's slice ----
    {
        const int i4 = blockIdx.x * 1024 + t;    // 0..16383 (float4 index)
        float4 v = reinterpret_cast<const float4*>(g_sims)[i4];
        unsigned int u0 = ford(v.x), u1 = ford(v.y), u2 = ford(v.z), u3 = ford(v.w);
        int base = i4 * 4;
        if (u0 >= T) { unsigned int p = atomicAdd(&g_ccnt, 1u); if (p < CAND_CAP)
            g_cand[p] = ((unsigned long long)u0 << 32) | (unsigned int)~(unsigned int)(base + 0); }
        if (u1 >= T) { unsigned int p = atomicAdd(&g_ccnt, 1u); if (p < CAND_CAP)
            g_cand[p] = ((unsigned long long)u1 << 32) | (unsigned int)~(unsigned int)(base + 1); }
        if (u2 >= T) { unsigned int p = atomicAdd(&g_ccnt, 1u); if (p < CAND_CAP)
            g_cand[p] = ((unsigned long long)u2 << 32) | (unsigned int)~(unsigned int)(base + 2); }
        if (u3 >= T) { unsigned int p = atomicAdd(&g_ccnt, 1u); if (p < CAND_CAP)
            g_cand[p] = ((unsigned long long)u3 << 32) | (unsigned int)~(unsigned int)(base + 3); }
    }

    // ---- last-block election ----
    __shared__ unsigned int s_is_last;
    __syncthreads();
    if (t == 0) {
        __threadfence();
        s_is_last = (atomicAdd(&g_done2, 1u) == gridDim.x - 1) ? 1u : 0u;
    }
    __syncthreads();
    if (!s_is_last) return;
    __threadfence();

    // ---- Phase C: exact ranking of ~540 candidates ----
    __shared__ unsigned long long s_key[CAND_CAP];
    const unsigned int ccnt = g_ccnt;
    const int cnt = (ccnt < CAND_CAP) ? (int)ccnt : CAND_CAP;

    for (int i = t; i < cnt; i += 1024) s_key[i] = g_cand[i];
    __syncthreads();

    for (int i = t; i < cnt; i += 1024) {
        const unsigned long long ki = s_key[i];
        int rank = 0;
        for (int j = 0; j < cnt; ++j)            // broadcast smem reads
            rank += (s_key[j] > ki);
        if (rank < KSEL)
            g_topk[rank] = (int)(~(unsigned int)(ki & 0xFFFFFFFFull));
    }

    // ---- re-arm scratch for the next invocation ----
    reinterpret_cast<uint4*>(g_hist)[t] = make_uint4(0u, 0u, 0u, 0u);  // 16 KB
    __syncthreads();
    if (t == 0) { g_ccnt = 0u; g_done2 = 0u; }
}

// ---------------------------------------------------------------------
// K3: out[b,k,:] = x[b,k,:] + prompts[topk[k], :]
// One block per (b,k) row; thread t handles float4 t of the row.
// x/out streamed (cs hints measured faster HERE: 83.3 -> 80.4us) so the
// 512 selected prompt rows (2 MB) stay L2-resident across all batches.
// ---------------------------------------------------------------------
__global__ void __launch_bounds__(256)
add_kernel(const float4* __restrict__ x,
           const float4* __restrict__ prompts,
           float4* __restrict__ out) {
    const int bid = blockIdx.x;            // b*512 + k
    const int k   = bid & (KSEL - 1);
    const int t   = threadIdx.x;           // 0..255
    const int row = g_topk[k];

    const size_t xo = (size_t)bid * (EMB / 4) + t;
    float4 xv = __ldcs(&x[xo]);                          // streaming read-once
    float4 pv = __ldg(&prompts[(size_t)row * (EMB / 4) + t]);
    xv.x += pv.x; xv.y += pv.y; xv.z += pv.z; xv.w += pv.w;
    __stcs(&out[xo], xv);                                // streaming write-once
}

// ---------------------------------------------------------------------
extern "C" void kernel_launch(void* const* d_in, const int* in_sizes, int n_in,
                              void* d_out, int out_size) {
    const float* x       = (const float*)d_in[0];   // [128, 512, 1024]
    const float* query   = (const float*)d_in[1];   // [1024]
    const float* keys    = (const float*)d_in[2];   // [65536, 1024]
    const float* prompts = (const float*)d_in[3];   // [65536, 1024]
    float* out           = (float*)d_out;           // [128, 512, 1024]

    sim_kernel<<<N_KEYS / 8, 256>>>(keys, query);
    compact_rank_kernel<<<16, 1024>>>();
    add_kernel<<<BATCH * KSEL, 256>>>(reinterpret_cast<const float4*>(x),
                                      reinterpret_cast<const float4*>(prompts),
                                      reinterpret_cast<float4*>(out));
}